// round 1
// baseline (speedup 1.0000x reference)
#include <cuda_runtime.h>

// ---------------- problem constants ----------------
#define BDIM 8
#define DDIM 256
#define TDIM 1024
#define NCODES 16384
#define BT 8192                      // B*T rows
#define DECAYF 0.99f
#define OMDF 0.01f                   // 1 - decay (fp32 of python 1.0-0.99)
#define EPSF 1e-5f

// ---------------- output layout (flattened tuple, float32) ----------------
// (out[B,D,T], perplexity, idx[BT], loss, new_weight[N,D], new_cluster_size[N], new_embed_avg[N,D])
#define OUT_OFF   0
#define PERP_OFF  2097152
#define IDX_OFF   2097153
#define LOSS_OFF  2105345
#define NW_OFF    2105346
#define NCS_OFF   6299650
#define NEA_OFF   6316034
#define TOTAL_OUT 10510338

// ---------------- scratch (device globals: no runtime allocs allowed) ----------------
__device__ float g_zf[BT * DDIM];                // z transposed to [BT, D]
__device__ float g_wh[NCODES];                   // 0.5 * ||w_n||^2
__device__ unsigned long long g_best[BT];        // packed (ordered score, ~n)
__device__ float g_counts[NCODES];
__device__ float g_loss;
__device__ float g_ntot;
__device__ float g_plex;
__device__ float g_A;                            // (ntot + N*eps)/ntot

// ---------------- init ----------------
__global__ void k_init() {
    int i = blockIdx.x * blockDim.x + threadIdx.x;     // 16384 threads
    if (i < NCODES) g_counts[i] = 0.0f;
    if (i < BT) g_best[i] = 0ull;
    if (i == 0) { g_loss = 0.0f; g_ntot = 0.0f; g_plex = 0.0f; }
}

// ---------------- transpose z[B,D,T] -> zf[BT,D] ----------------
__global__ void k_transpose(const float* __restrict__ z) {
    __shared__ float tile[32][33];
    int b = blockIdx.z;
    int t0 = blockIdx.x * 32;
    int d0 = blockIdx.y * 32;
    int x = threadIdx.x;
    #pragma unroll
    for (int yy = threadIdx.y; yy < 32; yy += 8)
        tile[yy][x] = z[b * (DDIM * TDIM) + (d0 + yy) * TDIM + t0 + x];
    __syncthreads();
    #pragma unroll
    for (int yy = threadIdx.y; yy < 32; yy += 8)
        g_zf[(b * TDIM + t0 + yy) * DDIM + d0 + x] = tile[x][yy];
}

// ---------------- wh[n] = 0.5*sum_d w^2 (one warp per row) ----------------
__global__ void k_wh(const float* __restrict__ W) {
    int warp = (blockIdx.x * blockDim.x + threadIdx.x) >> 5;
    int lane = threadIdx.x & 31;
    if (warp >= NCODES) return;
    const float4* row = reinterpret_cast<const float4*>(W + (size_t)warp * DDIM);
    float s = 0.0f;
    #pragma unroll
    for (int i = 0; i < 2; i++) {
        float4 v = row[lane + i * 32];
        s += v.x * v.x + v.y * v.y + v.z * v.z + v.w * v.w;
    }
    #pragma unroll
    for (int o = 16; o; o >>= 1) s += __shfl_xor_sync(0xFFFFFFFFu, s, o);
    if (lane == 0) g_wh[warp] = 0.5f * s;
}

// ---------------- main GEMM + fused argmax ----------------
#define MT 64
#define NT 128
#define KT 32
#define NSPLIT 2
#define BS_STRIDE 132
#define GEMM_SMEM ((MT * DDIM + 2 * KT * BS_STRIDE) * 4)

__global__ __launch_bounds__(256, 2) void k_gemm_argmax(const float* __restrict__ W) {
    extern __shared__ float smem[];
    float* As  = smem;                          // As[m*DDIM + k]  (A resident)
    float* Bs0 = smem + MT * DDIM;              // Bs[k*BS_STRIDE + n]
    float* Bs1 = Bs0 + KT * BS_STRIDE;

    const int tid = threadIdx.x;
    const int tx = tid & 15;
    const int ty = tid >> 4;
    const int row_base = ty * 4;
    const int col_base = tx * 8;
    const int m0 = blockIdx.x * MT;
    const int nbase = blockIdx.y * (NCODES / NSPLIT);
    const float4* W4 = reinterpret_cast<const float4*>(W);

    // load A tile once: 64 rows x 256 k, contiguous float4 copy
    {
        const float4* src = reinterpret_cast<const float4*>(g_zf) + (size_t)m0 * (DDIM / 4);
        float4* dst = reinterpret_cast<float4*>(As);
        #pragma unroll
        for (int i = 0; i < 16; i++) dst[tid + i * 256] = src[tid + i * 256];
    }

    float best_s[4];
    int best_n[4];
    #pragma unroll
    for (int i = 0; i < 4; i++) { best_s[i] = -3.4e38f; best_n[i] = 0; }

    auto loadB = [&](float* Bd, int n0, int k0) {
        #pragma unroll
        for (int i = 0; i < 4; i++) {
            int idx4 = tid + i * 256;
            int n  = idx4 >> 3;       // 0..127
            int k4 = idx4 & 7;        // float4 index within 32-k chunk
            float4 v = W4[(size_t)(n0 + n) * (DDIM / 4) + (k0 >> 2) + k4];
            float* p = Bd + (k4 * 4) * BS_STRIDE + n;
            p[0] = v.x; p[BS_STRIDE] = v.y; p[2 * BS_STRIDE] = v.z; p[3 * BS_STRIDE] = v.w;
        }
    };

    const int NTILES = (NCODES / NSPLIT) / NT;  // 64

    for (int nt = 0; nt < NTILES; nt++) {
        int n0 = nbase + nt * NT;
        float acc[4][8];
        #pragma unroll
        for (int i = 0; i < 4; i++)
            #pragma unroll
            for (int j = 0; j < 8; j++) acc[i][j] = 0.0f;

        loadB(Bs0, n0, 0);
        __syncthreads();

        #pragma unroll 1
        for (int kc = 0; kc < DDIM / KT; kc++) {
            float* Bcur = (kc & 1) ? Bs1 : Bs0;
            float* Bnxt = (kc & 1) ? Bs0 : Bs1;
            if (kc < DDIM / KT - 1) loadB(Bnxt, n0, (kc + 1) * KT);

            #pragma unroll
            for (int kk = 0; kk < KT; kk++) {
                int k = kc * KT + kk;
                float a0 = As[(row_base + 0) * DDIM + k];
                float a1 = As[(row_base + 1) * DDIM + k];
                float a2 = As[(row_base + 2) * DDIM + k];
                float a3 = As[(row_base + 3) * DDIM + k];
                float4 b0 = *reinterpret_cast<const float4*>(&Bcur[kk * BS_STRIDE + col_base]);
                float4 b1 = *reinterpret_cast<const float4*>(&Bcur[kk * BS_STRIDE + col_base + 4]);
                float bb[8] = {b0.x, b0.y, b0.z, b0.w, b1.x, b1.y, b1.z, b1.w};
                #pragma unroll
                for (int j = 0; j < 8; j++) {
                    acc[0][j] += a0 * bb[j];
                    acc[1][j] += a1 * bb[j];
                    acc[2][j] += a2 * bb[j];
                    acc[3][j] += a3 * bb[j];
                }
            }
            __syncthreads();
        }

        // epilogue: score = z.w - 0.5||w||^2, running argmax (ascending n, strict > keeps first)
        #pragma unroll
        for (int j = 0; j < 8; j++) {
            int n = n0 + col_base + j;
            float h = g_wh[n];
            #pragma unroll
            for (int i = 0; i < 4; i++) {
                float s = acc[i][j] - h;
                if (s > best_s[i]) { best_s[i] = s; best_n[i] = n; }
            }
        }
    }

    // reduce across the 16 tx threads sharing each row (xor within 16-lane half-warps)
    #pragma unroll
    for (int i = 0; i < 4; i++) {
        float s = best_s[i];
        int n = best_n[i];
        #pragma unroll
        for (int off = 8; off; off >>= 1) {
            float s2 = __shfl_xor_sync(0xFFFFFFFFu, s, off);
            int   n2 = __shfl_xor_sync(0xFFFFFFFFu, n, off);
            if (s2 > s || (s2 == s && n2 < n)) { s = s2; n = n2; }
        }
        if (tx == 0) {
            unsigned u = __float_as_uint(s);
            u = (u & 0x80000000u) ? ~u : (u | 0x80000000u);   // order-preserving encode
            unsigned long long key =
                ((unsigned long long)u << 32) | (unsigned)(0xFFFFFFFFu - (unsigned)n);
            atomicMax(&g_best[m0 + row_base + i], key);
        }
    }
}

// ---------------- new_embed_avg init: decay * embed_avg ----------------
__global__ void k_init_emb(const float* __restrict__ ea, float* __restrict__ out) {
    int stride = gridDim.x * blockDim.x;
    const float2* e2 = reinterpret_cast<const float2*>(ea);
    float2* o2 = reinterpret_cast<float2*>(out + NEA_OFF);
    for (int j = blockIdx.x * blockDim.x + threadIdx.x; j < NCODES * DDIM / 2; j += stride) {
        float2 v = e2[j];
        v.x *= DECAYF; v.y *= DECAYF;
        o2[j] = v;
    }
}

// ---------------- per-row: gather z_q, write out, scatter EMA, loss, counts, idx ----------------
__global__ void k_assign(const float* __restrict__ W, float* __restrict__ out) {
    __shared__ float red[8];
    int m = blockIdx.x;
    int d = threadIdx.x;
    unsigned long long key = g_best[m];
    int n = (int)(0xFFFFFFFFu - (unsigned)(key & 0xFFFFFFFFull));

    float wv = __ldg(&W[(size_t)n * DDIM + d]);
    float zv = g_zf[(size_t)m * DDIM + d];
    int b = m >> 10;           // T = 1024
    int t = m & 1023;
    out[OUT_OFF + b * (DDIM * TDIM) + d * TDIM + t] = wv;     // straight-through == z_q
    atomicAdd(&out[NEA_OFF + (size_t)n * DDIM + d], OMDF * zv);

    float diff = wv - zv;
    float sq = diff * diff;
    #pragma unroll
    for (int off = 16; off; off >>= 1) sq += __shfl_xor_sync(0xFFFFFFFFu, sq, off);
    if ((d & 31) == 0) red[d >> 5] = sq;
    __syncthreads();
    if (d == 0) {
        float v = 0.0f;
        #pragma unroll
        for (int i = 0; i < 8; i++) v += red[i];
        atomicAdd(&g_loss, v);
        atomicAdd(&g_counts[n], 1.0f);
        out[IDX_OFF + m] = (float)n;
    }
}

// ---------------- new_cluster_size + reductions for perplexity / ntot ----------------
__global__ void k_cs(const float* __restrict__ cs, float* __restrict__ out) {
    __shared__ float r1[8], r2[8];
    int n = blockIdx.x * blockDim.x + threadIdx.x;
    float ncs_v = 0.0f, term = 0.0f;
    if (n < NCODES) {
        float c = g_counts[n];
        ncs_v = DECAYF * cs[n] + OMDF * c;
        out[NCS_OFF + n] = ncs_v;
        float p = c * (1.0f / 8192.0f);
        term = p * logf(p + 1e-10f);
    }
    float a = ncs_v, bsum = term;
    #pragma unroll
    for (int off = 16; off; off >>= 1) {
        a += __shfl_xor_sync(0xFFFFFFFFu, a, off);
        bsum += __shfl_xor_sync(0xFFFFFFFFu, bsum, off);
    }
    int lane = threadIdx.x & 31, wid = threadIdx.x >> 5;
    if (lane == 0) { r1[wid] = a; r2[wid] = bsum; }
    __syncthreads();
    if (threadIdx.x == 0) {
        float sa = 0.0f, sb = 0.0f;
        #pragma unroll
        for (int i = 0; i < 8; i++) { sa += r1[i]; sb += r2[i]; }
        atomicAdd(&g_ntot, sa);
        atomicAdd(&g_plex, sb);
    }
}

// ---------------- scalars ----------------
__global__ void k_final(float* __restrict__ out) {
    out[PERP_OFF] = expf(-g_plex);
    out[LOSS_OFF] = 0.25f * g_loss * (1.0f / (float)(BT * DDIM));
    g_A = (g_ntot + (float)NCODES * EPSF) / g_ntot;
}

// ---------------- new_weight = nea * A / (ncs + eps) ----------------
__global__ void k_weight(float* __restrict__ out) {
    int stride = gridDim.x * blockDim.x;
    float A = g_A;
    const float2* nea2 = reinterpret_cast<const float2*>(out + NEA_OFF);
    float2* nw2 = reinterpret_cast<float2*>(out + NW_OFF);
    for (int j = blockIdx.x * blockDim.x + threadIdx.x; j < NCODES * DDIM / 2; j += stride) {
        int n = j >> 7;                      // (j*2) >> 8
        float inv = A / (out[NCS_OFF + n] + EPSF);
        float2 v = nea2[j];
        v.x *= inv; v.y *= inv;
        nw2[j] = v;
    }
}

// ---------------- launch ----------------
extern "C" void kernel_launch(void* const* d_in, const int* in_sizes, int n_in,
                              void* d_out, int out_size) {
    const float* z  = (const float*)d_in[0];
    const float* W  = (const float*)d_in[1];
    const float* cs = (const float*)d_in[2];
    const float* ea = (const float*)d_in[3];
    float* out = (float*)d_out;

    cudaFuncSetAttribute(k_gemm_argmax, cudaFuncAttributeMaxDynamicSharedMemorySize, GEMM_SMEM);

    k_init<<<64, 256>>>();
    k_transpose<<<dim3(TDIM / 32, DDIM / 32, BDIM), dim3(32, 8)>>>(z);
    k_wh<<<2048, 256>>>(W);
    k_gemm_argmax<<<dim3(BT / MT, NSPLIT), 256, GEMM_SMEM>>>(W);
    k_init_emb<<<4096, 256>>>(ea, out);
    k_assign<<<BT, DDIM>>>(W, out);
    k_cs<<<NCODES / 256, 256>>>(cs, out);
    k_final<<<1, 1>>>(out);
    k_weight<<<2048, 256>>>(out);
}

// round 3
// speedup vs baseline: 4.7505x; 4.7505x over previous
#include <cuda_runtime.h>
#include <cuda_fp16.h>
#include <cstdint>

// ---------------- problem constants ----------------
#define BDIM 8
#define DDIM 256
#define TDIM 1024
#define NCODES 16384
#define BT 8192
#define DECAYF 0.99f
#define OMDF 0.01f
#define EPSF 1e-5f

// ---------------- output layout (flattened tuple, float32) ----------------
#define OUT_OFF   0
#define PERP_OFF  2097152
#define IDX_OFF   2097153
#define LOSS_OFF  2105345
#define NW_OFF    2105346
#define NCS_OFF   6299650
#define NEA_OFF   6316034

// ---------------- scratch ----------------
__device__ float g_zf[BT * DDIM];
__device__ __half g_z16a[BT * DDIM];
__device__ __half g_z16b[BT * DDIM];
__device__ __half g_w16a[NCODES * DDIM];
__device__ __half g_w16b[NCODES * DDIM];
__device__ float g_wh[NCODES];
__device__ unsigned long long g_best[BT];
__device__ float g_counts[NCODES];
__device__ float g_loss;
__device__ float g_ntot;
__device__ float g_plex;
__device__ float g_A;

// ================= PTX helpers (baseline PTX only — no tcgen05) =================
__device__ __forceinline__ uint32_t smem_u32(const void* p) {
    uint32_t a;
    asm("{ .reg .u64 t; cvta.to.shared.u64 t, %1; cvt.u32.u64 %0, t; }" : "=r"(a) : "l"(p));
    return a;
}
__device__ __forceinline__ void cpa16(uint32_t dst, const void* src) {
    asm volatile("cp.async.cg.shared.global [%0], [%1], 16;"
                 :: "r"(dst), "l"(__cvta_generic_to_global(src)));
}
#define CP_COMMIT() asm volatile("cp.async.commit_group;" ::: "memory")
#define CP_WAIT1()  asm volatile("cp.async.wait_group 1;" ::: "memory")

__device__ __forceinline__ void ldsm4(uint32_t* r, uint32_t addr) {
    asm volatile("ldmatrix.sync.aligned.m8n8.x4.shared.b16 {%0,%1,%2,%3}, [%4];"
                 : "=r"(r[0]), "=r"(r[1]), "=r"(r[2]), "=r"(r[3]) : "r"(addr));
}
__device__ __forceinline__ void mma16816(float* c, const uint32_t* a, const uint32_t* b) {
    asm volatile(
        "mma.sync.aligned.m16n8k16.row.col.f32.f16.f16.f32 "
        "{%0,%1,%2,%3}, {%4,%5,%6,%7}, {%8,%9}, {%0,%1,%2,%3};"
        : "+f"(c[0]), "+f"(c[1]), "+f"(c[2]), "+f"(c[3])
        : "r"(a[0]), "r"(a[1]), "r"(a[2]), "r"(a[3]), "r"(b[0]), "r"(b[1]));
}

// ================= small kernels =================
__global__ void k_init() {
    int i = blockIdx.x * blockDim.x + threadIdx.x;
    if (i < NCODES) g_counts[i] = 0.0f;
    if (i < BT) g_best[i] = 0ull;
    if (i == 0) { g_loss = 0.0f; g_ntot = 0.0f; g_plex = 0.0f; }
}

// transpose z[B,D,T] -> zf[BT,D] fp32 + fp16 split (fused)
__global__ void k_transpose(const float* __restrict__ z) {
    __shared__ float tile[32][33];
    int b = blockIdx.z;
    int t0 = blockIdx.x * 32;
    int d0 = blockIdx.y * 32;
    int x = threadIdx.x;
    #pragma unroll
    for (int yy = threadIdx.y; yy < 32; yy += 8)
        tile[yy][x] = z[b * (DDIM * TDIM) + (d0 + yy) * TDIM + t0 + x];
    __syncthreads();
    #pragma unroll
    for (int yy = threadIdx.y; yy < 32; yy += 8) {
        float v = tile[x][yy];
        size_t o = (size_t)(b * TDIM + t0 + yy) * DDIM + d0 + x;
        g_zf[o] = v;
        __half h0 = __float2half_rn(v);
        g_z16a[o] = h0;
        g_z16b[o] = __float2half_rn(v - __half2float(h0));
    }
}

__global__ void k_wh(const float* __restrict__ W) {
    int warp = (blockIdx.x * blockDim.x + threadIdx.x) >> 5;
    int lane = threadIdx.x & 31;
    if (warp >= NCODES) return;
    const float4* row = reinterpret_cast<const float4*>(W + (size_t)warp * DDIM);
    float s = 0.0f;
    #pragma unroll
    for (int i = 0; i < 2; i++) {
        float4 v = row[lane + i * 32];
        s += v.x * v.x + v.y * v.y + v.z * v.z + v.w * v.w;
    }
    #pragma unroll
    for (int o = 16; o; o >>= 1) s += __shfl_xor_sync(0xFFFFFFFFu, s, o);
    if (lane == 0) g_wh[warp] = 0.5f * s;
}

__global__ void k_convert_w(const float* __restrict__ W) {
    int i = blockIdx.x * blockDim.x + threadIdx.x;     // float4 index, 1048576 total
    float4 v = reinterpret_cast<const float4*>(W)[i];
    __half h0x = __float2half_rn(v.x), h0y = __float2half_rn(v.y);
    __half h0z = __float2half_rn(v.z), h0w = __float2half_rn(v.w);
    __half h1x = __float2half_rn(v.x - __half2float(h0x));
    __half h1y = __float2half_rn(v.y - __half2float(h0y));
    __half h1z = __float2half_rn(v.z - __half2float(h0z));
    __half h1w = __float2half_rn(v.w - __half2float(h0w));
    __half2* a = reinterpret_cast<__half2*>(g_w16a);
    __half2* b = reinterpret_cast<__half2*>(g_w16b);
    a[2 * i] = __halves2half2(h0x, h0y); a[2 * i + 1] = __halves2half2(h0z, h0w);
    b[2 * i] = __halves2half2(h1x, h1y); b[2 * i + 1] = __halves2half2(h1z, h1w);
}

// ================= HMMA GEMM + fused argmax =================
// CTA: 128 m-rows, n-split of 8192 codes (blockIdx.y), 64 n-tiles of 128.
// A (both fp16 halves, all K=256) resident in smem: 8 blocks of 16KB.
// B streamed: chunk = (n-tile, k-chunk of 64) x 2 halves = 32KB; 3-stage cp.async ring.
// 3-term split: acc += A0*B0 + A1*B0 + A0*B1  (drops only a1*b1 ~ 2^-22)
#define A_OFF 0
#define B_OFF 131072
#define GEMM_SMEM 229376     // 128KB A + 3*32KB B ring
#define NSPLIT 2
#define NCHUNK 256           // 64 n-tiles * 4 k-chunks

__global__ __launch_bounds__(256, 1) void k_gemm_hmma() {
    extern __shared__ char smem[];
    const uint32_t sb = smem_u32(smem);
    const int tid = threadIdx.x;
    const int lane = tid & 31;
    const int wid = tid >> 5;
    const int wx = wid >> 1;          // 0..3  (m)
    const int wy = wid & 1;           // 0..1  (n)
    const int g = lane >> 2;
    const int t = lane & 3;
    const int m0 = blockIdx.x * 128;
    const int nsbase = blockIdx.y * (NCODES / NSPLIT);

    // ---- per-lane ldmatrix address pieces ----
    // A x4: lane row = m_base + (lane&15), k byte sel = (lane>>4)*16
    int aRow[2], aXor[2];
    #pragma unroll
    for (int mi = 0; mi < 2; mi++) {
        int r = wx * 32 + mi * 16 + (lane & 15);
        aRow[mi] = r * 128;
        aXor[mi] = (r & 7) << 4;
    }
    const int aKsel = (lane >> 4) * 16;
    // B x4: lane row = n_base + ((lane>>4)<<3) + (lane&7), k byte sel = ((lane>>3)&1)*16
    int bRow[4], bXor[4];
    #pragma unroll
    for (int nj = 0; nj < 4; nj++) {
        int r = wy * 64 + nj * 16 + ((lane >> 4) << 3) + (lane & 7);
        bRow[nj] = r * 128;
        bXor[nj] = (r & 7) << 4;
    }
    const int bKsel = ((lane >> 3) & 1) * 16;

    // ---- prologue: A (128KB) + chunk0 as group0; chunk1 as group1 ----
    {
        #pragma unroll
        for (int j = 0; j < 32; j++) {
            int q = tid + j * 256;              // 0..8191 16B-granules
            int blk = q >> 10;                  // p*4+kc
            int rem = q & 1023;
            int r = rem >> 3, cc = rem & 7;
            int p = blk >> 2, kc = blk & 3;
            const __half* src = (p ? g_z16b : g_z16a) +
                                (size_t)(m0 + r) * DDIM + kc * 64 + cc * 8;
            cpa16(sb + A_OFF + blk * 16384 + r * 128 + ((cc * 16) ^ ((r & 7) << 4)), src);
        }
    }
    auto loadB = [&](int c2, int s) {
        int nt = c2 >> 2, kc = c2 & 3;
        int n0 = nsbase + nt * 128;
        #pragma unroll
        for (int p = 0; p < 2; p++) {
            const __half* base = (p ? g_w16b : g_w16a);
            #pragma unroll
            for (int i = 0; i < 4; i++) {
                int q = tid + i * 256;          // 0..1023
                int r = q >> 3, cc = q & 7;
                const __half* src = base + (size_t)(n0 + r) * DDIM + kc * 64 + cc * 8;
                cpa16(sb + B_OFF + s * 32768 + p * 16384 + r * 128 +
                      ((cc * 16) ^ ((r & 7) << 4)), src);
            }
        }
    };
    loadB(0, 0);
    CP_COMMIT();
    loadB(1, 1);
    CP_COMMIT();

    float acc[2][8][4];
    #pragma unroll
    for (int mi = 0; mi < 2; mi++)
        #pragma unroll
        for (int ni = 0; ni < 8; ni++)
            #pragma unroll
            for (int q = 0; q < 4; q++) acc[mi][ni][q] = 0.0f;

    float bs[4];
    int bn[4];
    #pragma unroll
    for (int q = 0; q < 4; q++) { bs[q] = -3.4e38f; bn[q] = 0; }

    for (int c = 0; c < NCHUNK; c++) {
        CP_WAIT1();
        __syncthreads();
        if (c + 2 < NCHUNK) { loadB(c + 2, (c + 2) % 3); CP_COMMIT(); }

        const int kc = c & 3;
        const uint32_t bstage = sb + B_OFF + (c % 3) * 32768;
        const uint32_t ablk0 = sb + A_OFF + kc * 16384;          // h0
        const uint32_t ablk1 = ablk0 + 4 * 16384;                // h1

        #pragma unroll
        for (int kk = 0; kk < 4; kk++) {
            const int kbyteA = kk * 32 + aKsel;
            const int kbyteB = kk * 32 + bKsel;
            uint32_t af[2][2][4];
            #pragma unroll
            for (int mi = 0; mi < 2; mi++) {
                ldsm4(af[0][mi], ablk0 + aRow[mi] + (kbyteA ^ aXor[mi]));
                ldsm4(af[1][mi], ablk1 + aRow[mi] + (kbyteA ^ aXor[mi]));
            }
            uint32_t bf[2][4][4];
            #pragma unroll
            for (int p = 0; p < 2; p++) {
                const uint32_t bb = bstage + p * 16384;
                #pragma unroll
                for (int nj = 0; nj < 4; nj++)
                    ldsm4(bf[p][nj], bb + bRow[nj] + (kbyteB ^ bXor[nj]));
            }
            #pragma unroll
            for (int mi = 0; mi < 2; mi++)
                #pragma unroll
                for (int nj = 0; nj < 4; nj++) {
                    mma16816(acc[mi][2 * nj],     af[0][mi], &bf[0][nj][0]);
                    mma16816(acc[mi][2 * nj + 1], af[0][mi], &bf[0][nj][2]);
                    mma16816(acc[mi][2 * nj],     af[1][mi], &bf[0][nj][0]);
                    mma16816(acc[mi][2 * nj + 1], af[1][mi], &bf[0][nj][2]);
                    mma16816(acc[mi][2 * nj],     af[0][mi], &bf[1][nj][0]);
                    mma16816(acc[mi][2 * nj + 1], af[0][mi], &bf[1][nj][2]);
                }
        }

        if (kc == 3) {
            // epilogue for n-tile (c>>2): scores = acc - 0.5||w||^2; running argmax
            const int n0 = nsbase + (c >> 2) * 128 + wy * 64;
            #pragma unroll
            for (int mi = 0; mi < 2; mi++) {
                #pragma unroll
                for (int ni = 0; ni < 8; ni++) {
                    int n = n0 + ni * 8 + t * 2;
                    float w0 = __ldg(&g_wh[n]);
                    float w1 = __ldg(&g_wh[n + 1]);
                    float s0 = acc[mi][ni][0] - w0;
                    float s1 = acc[mi][ni][1] - w1;
                    float s2 = acc[mi][ni][2] - w0;
                    float s3 = acc[mi][ni][3] - w1;
                    if (s0 > bs[mi * 2])     { bs[mi * 2] = s0;     bn[mi * 2] = n; }
                    if (s1 > bs[mi * 2])     { bs[mi * 2] = s1;     bn[mi * 2] = n + 1; }
                    if (s2 > bs[mi * 2 + 1]) { bs[mi * 2 + 1] = s2; bn[mi * 2 + 1] = n; }
                    if (s3 > bs[mi * 2 + 1]) { bs[mi * 2 + 1] = s3; bn[mi * 2 + 1] = n + 1; }
                    acc[mi][ni][0] = 0.0f; acc[mi][ni][1] = 0.0f;
                    acc[mi][ni][2] = 0.0f; acc[mi][ni][3] = 0.0f;
                }
            }
        }
    }

    // ---- final reduce across the 4 lanes sharing each row, then atomicMax ----
    #pragma unroll
    for (int slot = 0; slot < 4; slot++) {
        float s = bs[slot];
        int n = bn[slot];
        #pragma unroll
        for (int off = 1; off <= 2; off <<= 1) {
            float s2 = __shfl_xor_sync(0xFFFFFFFFu, s, off);
            int   n2 = __shfl_xor_sync(0xFFFFFFFFu, n, off);
            if (s2 > s || (s2 == s && n2 < n)) { s = s2; n = n2; }
        }
        if (t == 0) {
            int row = m0 + wx * 32 + (slot >> 1) * 16 + g + (slot & 1) * 8;
            unsigned u = __float_as_uint(s);
            u = (u & 0x80000000u) ? ~u : (u | 0x80000000u);
            unsigned long long key =
                ((unsigned long long)u << 32) | (unsigned)(0xFFFFFFFFu - (unsigned)n);
            atomicMax(&g_best[row], key);
        }
    }
}

// ================= tail kernels =================
__global__ void k_init_emb(const float* __restrict__ ea, float* __restrict__ out) {
    int stride = gridDim.x * blockDim.x;
    const float2* e2 = reinterpret_cast<const float2*>(ea);
    float2* o2 = reinterpret_cast<float2*>(out + NEA_OFF);
    for (int j = blockIdx.x * blockDim.x + threadIdx.x; j < NCODES * DDIM / 2; j += stride) {
        float2 v = e2[j];
        v.x *= DECAYF; v.y *= DECAYF;
        o2[j] = v;
    }
}

__global__ void k_assign(const float* __restrict__ W, float* __restrict__ out) {
    __shared__ float red[8];
    int m = blockIdx.x;
    int d = threadIdx.x;
    unsigned long long key = g_best[m];
    int n = (int)(0xFFFFFFFFu - (unsigned)(key & 0xFFFFFFFFull));

    float wv = __ldg(&W[(size_t)n * DDIM + d]);
    float zv = g_zf[(size_t)m * DDIM + d];
    int b = m >> 10;
    int t = m & 1023;
    out[OUT_OFF + b * (DDIM * TDIM) + d * TDIM + t] = wv;
    atomicAdd(&out[NEA_OFF + (size_t)n * DDIM + d], OMDF * zv);

    float diff = wv - zv;
    float sq = diff * diff;
    #pragma unroll
    for (int off = 16; off; off >>= 1) sq += __shfl_xor_sync(0xFFFFFFFFu, sq, off);
    if ((d & 31) == 0) red[d >> 5] = sq;
    __syncthreads();
    if (d == 0) {
        float v = 0.0f;
        #pragma unroll
        for (int i = 0; i < 8; i++) v += red[i];
        atomicAdd(&g_loss, v);
        atomicAdd(&g_counts[n], 1.0f);
        out[IDX_OFF + m] = (float)n;
    }
}

__global__ void k_cs(const float* __restrict__ cs, float* __restrict__ out) {
    __shared__ float r1[8], r2[8];
    int n = blockIdx.x * blockDim.x + threadIdx.x;
    float ncs_v = 0.0f, term = 0.0f;
    if (n < NCODES) {
        float c = g_counts[n];
        ncs_v = DECAYF * cs[n] + OMDF * c;
        out[NCS_OFF + n] = ncs_v;
        float p = c * (1.0f / 8192.0f);
        term = p * logf(p + 1e-10f);
    }
    float a = ncs_v, bsum = term;
    #pragma unroll
    for (int off = 16; off; off >>= 1) {
        a += __shfl_xor_sync(0xFFFFFFFFu, a, off);
        bsum += __shfl_xor_sync(0xFFFFFFFFu, bsum, off);
    }
    int lane = threadIdx.x & 31, wd = threadIdx.x >> 5;
    if (lane == 0) { r1[wd] = a; r2[wd] = bsum; }
    __syncthreads();
    if (threadIdx.x == 0) {
        float sa = 0.0f, sbv = 0.0f;
        #pragma unroll
        for (int i = 0; i < 8; i++) { sa += r1[i]; sbv += r2[i]; }
        atomicAdd(&g_ntot, sa);
        atomicAdd(&g_plex, sbv);
    }
}

__global__ void k_final(float* __restrict__ out) {
    out[PERP_OFF] = expf(-g_plex);
    out[LOSS_OFF] = 0.25f * g_loss * (1.0f / (float)(BT * DDIM));
    g_A = (g_ntot + (float)NCODES * EPSF) / g_ntot;
}

__global__ void k_weight(float* __restrict__ out) {
    int stride = gridDim.x * blockDim.x;
    float A = g_A;
    const float2* nea2 = reinterpret_cast<const float2*>(out + NEA_OFF);
    float2* nw2 = reinterpret_cast<float2*>(out + NW_OFF);
    for (int j = blockIdx.x * blockDim.x + threadIdx.x; j < NCODES * DDIM / 2; j += stride) {
        int n = j >> 7;
        float inv = A / (out[NCS_OFF + n] + EPSF);
        float2 v = nea2[j];
        v.x *= inv; v.y *= inv;
        nw2[j] = v;
    }
}

// ================= launch =================
extern "C" void kernel_launch(void* const* d_in, const int* in_sizes, int n_in,
                              void* d_out, int out_size) {
    const float* z  = (const float*)d_in[0];
    const float* W  = (const float*)d_in[1];
    const float* cs = (const float*)d_in[2];
    const float* ea = (const float*)d_in[3];
    float* out = (float*)d_out;

    cudaFuncSetAttribute(k_gemm_hmma, cudaFuncAttributeMaxDynamicSharedMemorySize, GEMM_SMEM);

    k_init<<<64, 256>>>();
    k_transpose<<<dim3(TDIM / 32, DDIM / 32, BDIM), dim3(32, 8)>>>(z);
    k_wh<<<2048, 256>>>(W);
    k_convert_w<<<4096, 256>>>(W);
    k_gemm_hmma<<<dim3(BT / 128, NSPLIT), 256, GEMM_SMEM>>>();
    k_init_emb<<<4096, 256>>>(ea, out);
    k_assign<<<BT, DDIM>>>(W, out);
    k_cs<<<NCODES / 256, 256>>>(cs, out);
    k_final<<<1, 1>>>(out);
    k_weight<<<2048, 256>>>(out);
}

// round 4
// speedup vs baseline: 5.9915x; 1.2612x over previous
#include <cuda_runtime.h>
#include <cuda_fp16.h>
#include <cstdint>

// ---------------- problem constants ----------------
#define BDIM 8
#define DDIM 256
#define TDIM 1024
#define NCODES 16384
#define BT 8192
#define DECAYF 0.99f
#define OMDF 0.01f
#define EPSF 1e-5f
#define THRESH 1.25f

// ---------------- output layout (flattened tuple, float32) ----------------
#define OUT_OFF   0
#define PERP_OFF  2097152
#define IDX_OFF   2097153
#define LOSS_OFF  2105345
#define NW_OFF    2105346
#define NCS_OFF   6299650
#define NEA_OFF   6316034

// ---------------- scratch ----------------
#define CAP (1u << 22)                           // 4M candidate entries
__device__ float g_zf[BT * DDIM];
__device__ __half g_z16[BT * DDIM];              // fp16 of z (screening)
__device__ __half g_w16[NCODES * DDIM];          // fp16 of W (screening)
__device__ float g_wh[NCODES];                   // 0.5*||w||^2 fp32
__device__ unsigned long long g_best[BT];
__device__ unsigned g_amax[BT];                  // encoded approx row max
__device__ uint2 g_cand[CAP];                    // (row<<14|n, approx score bits)
__device__ unsigned g_ncand;
__device__ float g_counts[NCODES];
__device__ float g_loss;
__device__ float g_ntot;
__device__ float g_plex;
__device__ float g_A;

// ================= PTX helpers (baseline PTX only) =================
__device__ __forceinline__ uint32_t smem_u32(const void* p) {
    uint32_t a;
    asm("{ .reg .u64 t; cvta.to.shared.u64 t, %1; cvt.u32.u64 %0, t; }" : "=r"(a) : "l"(p));
    return a;
}
__device__ __forceinline__ void cpa16(uint32_t dst, const void* src) {
    asm volatile("cp.async.cg.shared.global [%0], [%1], 16;"
                 :: "r"(dst), "l"(__cvta_generic_to_global(src)));
}
#define CP_COMMIT() asm volatile("cp.async.commit_group;" ::: "memory")
#define CP_WAIT2()  asm volatile("cp.async.wait_group 2;" ::: "memory")
#define CP_WAIT0()  asm volatile("cp.async.wait_group 0;" ::: "memory")

__device__ __forceinline__ void ldsm4(uint32_t* r, uint32_t addr) {
    asm volatile("ldmatrix.sync.aligned.m8n8.x4.shared.b16 {%0,%1,%2,%3}, [%4];"
                 : "=r"(r[0]), "=r"(r[1]), "=r"(r[2]), "=r"(r[3]) : "r"(addr));
}
__device__ __forceinline__ void mma16816(float* c, const uint32_t* a, const uint32_t* b) {
    asm volatile(
        "mma.sync.aligned.m16n8k16.row.col.f32.f16.f16.f32 "
        "{%0,%1,%2,%3}, {%4,%5,%6,%7}, {%8,%9}, {%0,%1,%2,%3};"
        : "+f"(c[0]), "+f"(c[1]), "+f"(c[2]), "+f"(c[3])
        : "r"(a[0]), "r"(a[1]), "r"(a[2]), "r"(a[3]), "r"(b[0]), "r"(b[1]));
}

// monotone float<->uint encoding (s1 > s2 <=> enc(s1) > enc(s2))
__device__ __forceinline__ unsigned encf(float s) {
    unsigned u = __float_as_uint(s);
    return (u & 0x80000000u) ? ~u : (u | 0x80000000u);
}
__device__ __forceinline__ float decf(unsigned u) {
    return (u & 0x80000000u) ? __uint_as_float(u ^ 0x80000000u) : __uint_as_float(~u);
}

// ================= small kernels =================
__global__ void k_init() {
    int i = blockIdx.x * blockDim.x + threadIdx.x;
    if (i < NCODES) g_counts[i] = 0.0f;
    if (i < BT) { g_best[i] = 0ull; g_amax[i] = 0u; }
    if (i == 0) { g_loss = 0.0f; g_ntot = 0.0f; g_plex = 0.0f; g_ncand = 0u; }
}

// transpose z[B,D,T] -> zf[BT,D] fp32 + fp16 (fused)
__global__ void k_transpose(const float* __restrict__ z) {
    __shared__ float tile[32][33];
    int b = blockIdx.z;
    int t0 = blockIdx.x * 32;
    int d0 = blockIdx.y * 32;
    int x = threadIdx.x;
    #pragma unroll
    for (int yy = threadIdx.y; yy < 32; yy += 8)
        tile[yy][x] = z[b * (DDIM * TDIM) + (d0 + yy) * TDIM + t0 + x];
    __syncthreads();
    #pragma unroll
    for (int yy = threadIdx.y; yy < 32; yy += 8) {
        float v = tile[x][yy];
        size_t o = (size_t)(b * TDIM + t0 + yy) * DDIM + d0 + x;
        g_zf[o] = v;
        g_z16[o] = __float2half_rn(v);
    }
}

__global__ void k_wh(const float* __restrict__ W) {
    int warp = (blockIdx.x * blockDim.x + threadIdx.x) >> 5;
    int lane = threadIdx.x & 31;
    if (warp >= NCODES) return;
    const float4* row = reinterpret_cast<const float4*>(W + (size_t)warp * DDIM);
    float s = 0.0f;
    #pragma unroll
    for (int i = 0; i < 2; i++) {
        float4 v = row[lane + i * 32];
        s += v.x * v.x + v.y * v.y + v.z * v.z + v.w * v.w;
    }
    #pragma unroll
    for (int o = 16; o; o >>= 1) s += __shfl_xor_sync(0xFFFFFFFFu, s, o);
    if (lane == 0) g_wh[warp] = 0.5f * s;
}

__global__ void k_convert_w(const float* __restrict__ W) {
    int i = blockIdx.x * blockDim.x + threadIdx.x;     // float4 index, 1048576 total
    float4 v = reinterpret_cast<const float4*>(W)[i];
    __half2* a = reinterpret_cast<__half2*>(g_w16);
    a[2 * i]     = __halves2half2(__float2half_rn(v.x), __float2half_rn(v.y));
    a[2 * i + 1] = __halves2half2(__float2half_rn(v.z), __float2half_rn(v.w));
}

// ================= screening GEMM (1-term fp16) + candidate collection =================
// CTA: 128 m-rows, n-split 8192 codes, 64 n-tiles of 128, 4 k-chunks of 64.
// smem: [0,512) rowmax (encoded uint), [1024,66560) A h0 4x16KB, [66560,132096) B ring 4x16KB.
#define RM_OFF 0
#define A_OFF 1024
#define B_OFF 66560
#define GEMM_SMEM 132096
#define NSPLIT 2
#define NCHUNK 256           // 64 n-tiles * 4 k-chunks

__global__ __launch_bounds__(256, 1) void k_gemm_screen() {
    extern __shared__ char smem[];
    const uint32_t sb = smem_u32(smem);
    unsigned* rowmaxU = reinterpret_cast<unsigned*>(smem + RM_OFF);
    const int tid = threadIdx.x;
    const int lane = tid & 31;
    const int wid = tid >> 5;
    const int wx = wid >> 1;          // 0..3  (m)
    const int wy = wid & 1;           // 0..1  (n)
    const int g = lane >> 2;
    const int t = lane & 3;
    const int m0 = blockIdx.x * 128;
    const int nsbase = blockIdx.y * (NCODES / NSPLIT);

    if (tid < 128) rowmaxU[tid] = 0u;

    // ---- per-lane ldmatrix address pieces ----
    int aRow[2], aXor[2];
    #pragma unroll
    for (int mi = 0; mi < 2; mi++) {
        int r = wx * 32 + mi * 16 + (lane & 15);
        aRow[mi] = r * 128;
        aXor[mi] = (r & 7) << 4;
    }
    const int aKsel = (lane >> 4) * 16;
    int bRow[4], bXor[4];
    #pragma unroll
    for (int nj = 0; nj < 4; nj++) {
        int r = wy * 64 + nj * 16 + ((lane >> 4) << 3) + (lane & 7);
        bRow[nj] = r * 128;
        bXor[nj] = (r & 7) << 4;
    }
    const int bKsel = ((lane >> 3) & 1) * 16;

    // ---- prologue: A (64KB, h0) grouped with chunk0; then chunks 1,2 ----
    {
        #pragma unroll
        for (int j = 0; j < 16; j++) {
            int q = tid + j * 256;              // 0..4095 16B-granules
            int kc = q >> 10;
            int rem = q & 1023;
            int r = rem >> 3, cc = rem & 7;
            const __half* src = g_z16 + (size_t)(m0 + r) * DDIM + kc * 64 + cc * 8;
            cpa16(sb + A_OFF + kc * 16384 + r * 128 + ((cc * 16) ^ ((r & 7) << 4)), src);
        }
    }
    auto loadB = [&](int c2, int s) {
        int nt = c2 >> 2, kc = c2 & 3;
        int n0 = nsbase + nt * 128;
        #pragma unroll
        for (int i = 0; i < 4; i++) {
            int q = tid + i * 256;              // 0..1023
            int r = q >> 3, cc = q & 7;
            const __half* src = g_w16 + (size_t)(n0 + r) * DDIM + kc * 64 + cc * 8;
            cpa16(sb + B_OFF + s * 16384 + r * 128 + ((cc * 16) ^ ((r & 7) << 4)), src);
        }
    };
    loadB(0, 0); CP_COMMIT();
    loadB(1, 1); CP_COMMIT();
    loadB(2, 2); CP_COMMIT();

    float acc[2][8][4];
    #pragma unroll
    for (int mi = 0; mi < 2; mi++)
        #pragma unroll
        for (int ni = 0; ni < 8; ni++)
            #pragma unroll
            for (int q = 0; q < 4; q++) acc[mi][ni][q] = 0.0f;

    float bs[4];
    #pragma unroll
    for (int q = 0; q < 4; q++) bs[q] = -3.4e38f;

    // local row indices per slot (slot = mi*2 + upper-half)
    int rl[4];
    #pragma unroll
    for (int s = 0; s < 4; s++) rl[s] = wx * 32 + (s >> 1) * 16 + g + (s & 1) * 8;

    for (int c = 0; c < NCHUNK; c++) {
        if (c < NCHUNK - 3) { CP_WAIT2(); } else { CP_WAIT0(); }
        __syncthreads();
        if (c + 3 < NCHUNK) { loadB(c + 3, (c + 3) & 3); CP_COMMIT(); }

        const int kc = c & 3;
        const uint32_t bstage = sb + B_OFF + (c & 3) * 16384;
        const uint32_t ablk = sb + A_OFF + kc * 16384;

        #pragma unroll
        for (int kk = 0; kk < 4; kk++) {
            const int kbyteA = kk * 32 + aKsel;
            const int kbyteB = kk * 32 + bKsel;
            uint32_t af[2][4];
            #pragma unroll
            for (int mi = 0; mi < 2; mi++)
                ldsm4(af[mi], ablk + aRow[mi] + (kbyteA ^ aXor[mi]));
            uint32_t bf[4][4];
            #pragma unroll
            for (int nj = 0; nj < 4; nj++)
                ldsm4(bf[nj], bstage + bRow[nj] + (kbyteB ^ bXor[nj]));
            #pragma unroll
            for (int mi = 0; mi < 2; mi++)
                #pragma unroll
                for (int nj = 0; nj < 4; nj++) {
                    mma16816(acc[mi][2 * nj],     af[mi], &bf[nj][0]);
                    mma16816(acc[mi][2 * nj + 1], af[mi], &bf[nj][2]);
                }
        }

        if (kc == 3) {
            const int n0 = nsbase + (c >> 2) * 128 + wy * 64;
            // phase 1: convert acc -> scores, per-slot max, publish to smem rowmax
            float smax[4] = { -3.4e38f, -3.4e38f, -3.4e38f, -3.4e38f };
            #pragma unroll
            for (int ni = 0; ni < 8; ni++) {
                int n = n0 + ni * 8 + t * 2;
                float w0 = __ldg(&g_wh[n]);
                float w1 = __ldg(&g_wh[n + 1]);
                #pragma unroll
                for (int mi = 0; mi < 2; mi++) {
                    float s0 = acc[mi][ni][0] - w0;
                    float s1 = acc[mi][ni][1] - w1;
                    float s2 = acc[mi][ni][2] - w0;
                    float s3 = acc[mi][ni][3] - w1;
                    acc[mi][ni][0] = s0; acc[mi][ni][1] = s1;
                    acc[mi][ni][2] = s2; acc[mi][ni][3] = s3;
                    smax[mi * 2]     = fmaxf(smax[mi * 2],     fmaxf(s0, s1));
                    smax[mi * 2 + 1] = fmaxf(smax[mi * 2 + 1], fmaxf(s2, s3));
                }
            }
            #pragma unroll
            for (int s = 0; s < 4; s++) {
                bs[s] = fmaxf(bs[s], smax[s]);
                atomicMax(&rowmaxU[rl[s]], encf(smax[s]));
            }
            __syncthreads();
            // phase 2: collect candidates within THRESH of the shared row max
            float rth[4];
            #pragma unroll
            for (int s = 0; s < 4; s++) rth[s] = decf(rowmaxU[rl[s]]) - THRESH;
            #pragma unroll
            for (int ni = 0; ni < 8; ni++) {
                int n = n0 + ni * 8 + t * 2;
                #pragma unroll
                for (int mi = 0; mi < 2; mi++) {
                    #pragma unroll
                    for (int q = 0; q < 4; q++) {
                        float s = acc[mi][ni][q];
                        int slot = mi * 2 + (q >> 1);
                        if (s > rth[slot]) {
                            unsigned p = atomicAdd(&g_ncand, 1u);
                            if (p < CAP)
                                g_cand[p] = make_uint2(
                                    ((unsigned)(m0 + rl[slot]) << 14) | (unsigned)(n + (q & 1)),
                                    __float_as_uint(s));
                        }
                        acc[mi][ni][q] = 0.0f;
                    }
                }
            }
        }
    }

    // publish final per-row approx max (reduce across the 4 t-lanes of each row)
    #pragma unroll
    for (int s = 0; s < 4; s++) {
        float v = bs[s];
        #pragma unroll
        for (int off = 1; off <= 2; off <<= 1)
            v = fmaxf(v, __shfl_xor_sync(0xFFFFFFFFu, v, off));
        if (t == 0) atomicMax(&g_amax[m0 + rl[s]], encf(v));
    }
}

// ================= exact rescore of surviving candidates =================
__global__ void k_rescore(const float* __restrict__ W) {
    const int lane = threadIdx.x & 31;
    const unsigned warp = (blockIdx.x * blockDim.x + threadIdx.x) >> 5;
    const unsigned nwarps = (gridDim.x * blockDim.x) >> 5;
    unsigned count = g_ncand;
    if (count > CAP) count = CAP;
    for (unsigned c = warp; c < count; c += nwarps) {
        uint2 e = g_cand[c];
        unsigned row = e.x >> 14, n = e.x & 16383u;
        float sa = __uint_as_float(e.y);
        float amax = decf(g_amax[row]);
        if (sa < amax - THRESH) continue;              // filter vs final approx max
        const float4* zr = reinterpret_cast<const float4*>(g_zf + (size_t)row * DDIM);
        const float4* wr = reinterpret_cast<const float4*>(W + (size_t)n * DDIM);
        float s = 0.0f;
        #pragma unroll
        for (int i = 0; i < 2; i++) {
            float4 a = __ldg(&zr[lane + 32 * i]);
            float4 b = __ldg(&wr[lane + 32 * i]);
            s += a.x * b.x + a.y * b.y + a.z * b.z + a.w * b.w;
        }
        #pragma unroll
        for (int off = 16; off; off >>= 1) s += __shfl_xor_sync(0xFFFFFFFFu, s, off);
        if (lane == 0) {
            s -= __ldg(&g_wh[n]);
            unsigned u = encf(s);
            unsigned long long key =
                ((unsigned long long)u << 32) | (unsigned)(0xFFFFFFFFu - n);
            atomicMax(&g_best[row], key);
        }
    }
}

// ================= tail kernels =================
__global__ void k_init_emb(const float* __restrict__ ea, float* __restrict__ out) {
    int stride = gridDim.x * blockDim.x;
    const float2* e2 = reinterpret_cast<const float2*>(ea);
    float2* o2 = reinterpret_cast<float2*>(out + NEA_OFF);
    for (int j = blockIdx.x * blockDim.x + threadIdx.x; j < NCODES * DDIM / 2; j += stride) {
        float2 v = e2[j];
        v.x *= DECAYF; v.y *= DECAYF;
        o2[j] = v;
    }
}

__global__ void k_assign(const float* __restrict__ W, float* __restrict__ out) {
    __shared__ float red[8];
    int m = blockIdx.x;
    int d = threadIdx.x;
    unsigned long long key = g_best[m];
    int n = (int)(0xFFFFFFFFu - (unsigned)(key & 0xFFFFFFFFull));

    float wv = __ldg(&W[(size_t)n * DDIM + d]);
    float zv = g_zf[(size_t)m * DDIM + d];
    int b = m >> 10;
    int t = m & 1023;
    out[OUT_OFF + b * (DDIM * TDIM) + d * TDIM + t] = wv;
    atomicAdd(&out[NEA_OFF + (size_t)n * DDIM + d], OMDF * zv);

    float diff = wv - zv;
    float sq = diff * diff;
    #pragma unroll
    for (int off = 16; off; off >>= 1) sq += __shfl_xor_sync(0xFFFFFFFFu, sq, off);
    if ((d & 31) == 0) red[d >> 5] = sq;
    __syncthreads();
    if (d == 0) {
        float v = 0.0f;
        #pragma unroll
        for (int i = 0; i < 8; i++) v += red[i];
        atomicAdd(&g_loss, v);
        atomicAdd(&g_counts[n], 1.0f);
        out[IDX_OFF + m] = (float)n;
    }
}

__global__ void k_cs(const float* __restrict__ cs, float* __restrict__ out) {
    __shared__ float r1[8], r2[8];
    int n = blockIdx.x * blockDim.x + threadIdx.x;
    float ncs_v = 0.0f, term = 0.0f;
    if (n < NCODES) {
        float c = g_counts[n];
        ncs_v = DECAYF * cs[n] + OMDF * c;
        out[NCS_OFF + n] = ncs_v;
        float p = c * (1.0f / 8192.0f);
        term = p * logf(p + 1e-10f);
    }
    float a = ncs_v, bsum = term;
    #pragma unroll
    for (int off = 16; off; off >>= 1) {
        a += __shfl_xor_sync(0xFFFFFFFFu, a, off);
        bsum += __shfl_xor_sync(0xFFFFFFFFu, bsum, off);
    }
    int lane = threadIdx.x & 31, wd = threadIdx.x >> 5;
    if (lane == 0) { r1[wd] = a; r2[wd] = bsum; }
    __syncthreads();
    if (threadIdx.x == 0) {
        float sa = 0.0f, sbv = 0.0f;
        #pragma unroll
        for (int i = 0; i < 8; i++) { sa += r1[i]; sbv += r2[i]; }
        atomicAdd(&g_ntot, sa);
        atomicAdd(&g_plex, sbv);
    }
}

__global__ void k_final(float* __restrict__ out) {
    out[PERP_OFF] = expf(-g_plex);
    out[LOSS_OFF] = 0.25f * g_loss * (1.0f / (float)(BT * DDIM));
    g_A = (g_ntot + (float)NCODES * EPSF) / g_ntot;
}

__global__ void k_weight(float* __restrict__ out) {
    int stride = gridDim.x * blockDim.x;
    float A = g_A;
    const float2* nea2 = reinterpret_cast<const float2*>(out + NEA_OFF);
    float2* nw2 = reinterpret_cast<float2*>(out + NW_OFF);
    for (int j = blockIdx.x * blockDim.x + threadIdx.x; j < NCODES * DDIM / 2; j += stride) {
        int n = j >> 7;
        float inv = A / (out[NCS_OFF + n] + EPSF);
        float2 v = nea2[j];
        v.x *= inv; v.y *= inv;
        nw2[j] = v;
    }
}

// ================= launch =================
extern "C" void kernel_launch(void* const* d_in, const int* in_sizes, int n_in,
                              void* d_out, int out_size) {
    const float* z  = (const float*)d_in[0];
    const float* W  = (const float*)d_in[1];
    const float* cs = (const float*)d_in[2];
    const float* ea = (const float*)d_in[3];
    float* out = (float*)d_out;

    cudaFuncSetAttribute(k_gemm_screen, cudaFuncAttributeMaxDynamicSharedMemorySize, GEMM_SMEM);

    k_init<<<64, 256>>>();
    k_transpose<<<dim3(TDIM / 32, DDIM / 32, BDIM), dim3(32, 8)>>>(z);
    k_wh<<<2048, 256>>>(W);
    k_convert_w<<<4096, 256>>>(W);
    k_gemm_screen<<<dim3(BT / 128, NSPLIT), 256, GEMM_SMEM>>>();
    k_rescore<<<592, 256>>>(W);
    k_init_emb<<<4096, 256>>>(ea, out);
    k_assign<<<BT, DDIM>>>(W, out);
    k_cs<<<NCODES / 256, 256>>>(cs, out);
    k_final<<<1, 1>>>(out);
    k_weight<<<2048, 256>>>(out);
}